// round 3
// baseline (speedup 1.0000x reference)
#include <cuda_runtime.h>
#include <cstdint>
#include <cstddef>

// ---------------------------------------------------------------------------
// ProxyMLS loss, fused as:
//   K1a: pack A[i, 0:64]=e^2, A[i,64:128]=e               (N x 128)
//   K1b: pack B[j, 0:64]=w,  B[j,64:128]=-2*mu*w, cst[j]  (C x 128), zero accums
//   K2 : score = -0.5*(A @ B^T + cst)  -> g_score, + global min (for m)
//   K3 : per-class pos/neg exp sums + counts
//   K4 : log1p reduction -> scalar
// ---------------------------------------------------------------------------

#define N_ 4096
#define C_ 8192
#define D_ 64
#define KP 128

static __device__ __constant__ float kALPHA  = 32.0f;
static __device__ __constant__ float kMARGIN = 0.1f;

// device scratch (static globals: allocation-free)
__device__ float    g_A[(size_t)N_ * KP];         //  2 MiB
__device__ float    g_B[(size_t)C_ * KP];         //  4 MiB
__device__ float    g_cst[C_];
__device__ float    g_score[(size_t)N_ * C_];     // 128 MiB
__device__ unsigned g_min_u;
__device__ float    g_pos[C_];
__device__ float    g_neg[C_];
__device__ int      g_cnt[C_];

// monotone float <-> unsigned encoding (for atomicMin over floats)
__device__ __forceinline__ unsigned enc_f(float f) {
    unsigned b = __float_as_uint(f);
    return (b & 0x80000000u) ? ~b : (b ^ 0x80000000u);
}
__device__ __forceinline__ float dec_f(unsigned u) {
    unsigned b = (u & 0x80000000u) ? (u ^ 0x80000000u) : ~u;
    return __uint_as_float(b);
}

// packed fp32x2 FMA (Blackwell sm_100+; 2x fp32 throughput, PTX-only)
#define FMA2(d, a, b) asm("fma.rn.f32x2 %0, %1, %2, %0;" : "+l"(d) : "l"(a), "l"(b))

// ---------------------------------------------------------------------------
// K1a: pack embeddings
__global__ void k_prep_a(const float* __restrict__ emb) {
    int idx = blockIdx.x * 256 + threadIdx.x;   // exactly N_*D_ threads
    int i = idx >> 6;
    int d = idx & 63;
    float e = emb[idx];
    g_A[(size_t)i * KP + d]      = e * e;
    g_A[(size_t)i * KP + 64 + d] = e;
}

// K1b: pack proxies, per-class const, zero accumulators (1 warp per class)
__global__ void k_prep_b(const float* __restrict__ mu_, const float* __restrict__ lv_) {
    int j = blockIdx.x;
    int lane = threadIdx.x;
    float s = 0.0f;
#pragma unroll
    for (int t = 0; t < 2; t++) {
        int d = lane + t * 32;
        float lv = lv_[(size_t)j * D_ + d];
        float mu = mu_[(size_t)j * D_ + d];
        float w  = __expf(-lv);
        g_B[(size_t)j * KP + d]      = w;
        g_B[(size_t)j * KP + 64 + d] = -2.0f * mu * w;
        s += mu * mu * w + lv;
    }
#pragma unroll
    for (int o = 16; o > 0; o >>= 1) s += __shfl_xor_sync(0xffffffffu, s, o);
    if (lane == 0) {
        g_cst[j] = s;
        g_pos[j] = 0.0f;
        g_neg[j] = 0.0f;
        g_cnt[j] = 0;
        if (j == 0) g_min_u = 0xFFFFFFFFu;
    }
}

// ---------------------------------------------------------------------------
// K2: 128x128 block tile, 256 threads, 8x8 per thread via f32x2 pairs.
// A duplicated in SMEM so the (a,a) operand is a single LDS.64.
#define BM 128
#define BN 128
#define BK 64
#define PAD 258   // AsD pitch in floats (2*BM + 2): even -> 8B aligned u64 loads
#define PB  130   // Bs pitch in floats

__global__ void __launch_bounds__(256, 1) k_gemm() {
    extern __shared__ float smem_buf[];
    float* AsD = smem_buf;               // [BK][PAD]  (duplicated A)
    float* Bs  = smem_buf + BK * PAD;    // [BK][PB]

    const int tid = threadIdx.x;
    const int tx  = tid & 15;
    const int ty  = tid >> 4;
    const int m0  = blockIdx.y * BM;
    const int n0  = blockIdx.x * BN;

    unsigned long long acc[8][4];
#pragma unroll
    for (int r = 0; r < 8; r++)
#pragma unroll
        for (int g = 0; g < 4; g++) acc[r][g] = 0ull;

    for (int kc = 0; kc < KP; kc += BK) {
        // ---- load A tile (duplicated) ----
#pragma unroll
        for (int t = 0; t < 8; t++) {
            int fid = tid + t * 256;
            int row = fid >> 4;
            int kq  = fid & 15;
            float4 v = *(const float4*)&g_A[(size_t)(m0 + row) * KP + kc + kq * 4];
            int kb = kq * 4;
            AsD[(kb + 0) * PAD + 2 * row] = v.x; AsD[(kb + 0) * PAD + 2 * row + 1] = v.x;
            AsD[(kb + 1) * PAD + 2 * row] = v.y; AsD[(kb + 1) * PAD + 2 * row + 1] = v.y;
            AsD[(kb + 2) * PAD + 2 * row] = v.z; AsD[(kb + 2) * PAD + 2 * row + 1] = v.z;
            AsD[(kb + 3) * PAD + 2 * row] = v.w; AsD[(kb + 3) * PAD + 2 * row + 1] = v.w;
        }
        // ---- load B tile ----
#pragma unroll
        for (int t = 0; t < 8; t++) {
            int fid = tid + t * 256;
            int row = fid >> 4;
            int kq  = fid & 15;
            float4 v = *(const float4*)&g_B[(size_t)(n0 + row) * KP + kc + kq * 4];
            int kb = kq * 4;
            Bs[(kb + 0) * PB + row] = v.x;
            Bs[(kb + 1) * PB + row] = v.y;
            Bs[(kb + 2) * PB + row] = v.z;
            Bs[(kb + 3) * PB + row] = v.w;
        }
        __syncthreads();

#pragma unroll 16
        for (int k = 0; k < BK; k++) {
            const float* ar = AsD + k * PAD + ty * 4;  // dup'd: row_local = h*32 + ty*2 + rr
            const float* br = Bs  + k * PB  + tx * 2;  // col pair at g*32 + tx*2
            unsigned long long av[8], bv[4];
#pragma unroll
            for (int g = 0; g < 4; g++)
                bv[g] = *(const unsigned long long*)(br + g * 32);
#pragma unroll
            for (int h = 0; h < 4; h++) {
                av[2 * h]     = *(const unsigned long long*)(ar + h * 64);
                av[2 * h + 1] = *(const unsigned long long*)(ar + h * 64 + 2);
            }
#pragma unroll
            for (int r = 0; r < 8; r++)
#pragma unroll
                for (int g = 0; g < 4; g++)
                    FMA2(acc[r][g], av[r], bv[g]);
        }
        __syncthreads();
    }

    // ---- epilogue: score = -0.5*(dot + cst), store + global min ----
    const int cb = n0 + tx * 2;
    float2 cst[4];
#pragma unroll
    for (int g = 0; g < 4; g++)
        cst[g] = *(const float2*)&g_cst[cb + g * 32];

    float mn = 3.402823466e38f;
#pragma unroll
    for (int h = 0; h < 4; h++) {
#pragma unroll
        for (int rr = 0; rr < 2; rr++) {
            int row = m0 + h * 32 + ty * 2 + rr;
            int r = h * 2 + rr;
            float* dst = &g_score[(size_t)row * C_ + cb];
#pragma unroll
            for (int g = 0; g < 4; g++) {
                float lo = __uint_as_float((unsigned)(acc[r][g] & 0xffffffffu));
                float hi = __uint_as_float((unsigned)(acc[r][g] >> 32));
                float s0 = -0.5f * (lo + cst[g].x);
                float s1 = -0.5f * (hi + cst[g].y);
                mn = fminf(mn, fminf(s0, s1));
                *(float2*)(dst + g * 32) = make_float2(s0, s1);
            }
        }
    }

#pragma unroll
    for (int o = 16; o > 0; o >>= 1)
        mn = fminf(mn, __shfl_xor_sync(0xffffffffu, mn, o));
    __shared__ float smin[8];
    if ((tid & 31) == 0) smin[tid >> 5] = mn;
    __syncthreads();
    if (tid < 8) {
        mn = smin[tid];
#pragma unroll
        for (int o = 4; o > 0; o >>= 1)
            mn = fminf(mn, __shfl_xor_sync(0xffu, mn, o));
        if (tid == 0) atomicMin(&g_min_u, enc_f(mn));
    }
}

// ---------------------------------------------------------------------------
// K3: per-class exp sums. block = 128 cols, grid.y splits rows (512 each).
__global__ void k_colsum(const int* __restrict__ labels) {
    const int j = blockIdx.x * 128 + threadIdx.x;
    const float mm = -kALPHA * (dec_f(g_min_u) - kMARGIN);  // m = max(pos_e)
    float pos = 0.0f, neg = 0.0f;
    int cnt = 0;
    const int i0 = blockIdx.y * 512;
    const float* col = g_score + (size_t)i0 * C_ + j;
#pragma unroll 4
    for (int i = 0; i < 512; i++) {
        float x  = col[(size_t)i * C_];
        int lab  = labels[i0 + i];
        if (lab == j) {
            pos += __expf(-kALPHA * (x - kMARGIN) - mm);
            cnt++;
        } else {
            float tn = kALPHA * (x + kMARGIN) - mm;
            if (tn > -87.0f) neg += __expf(tn);
        }
    }
    if (cnt) {
        atomicAdd(&g_cnt[j], cnt);
        atomicAdd(&g_pos[j], pos);
    }
    if (neg != 0.0f) atomicAdd(&g_neg[j], neg);
}

// ---------------------------------------------------------------------------
// K4: final scalar
__global__ void k_final(float* __restrict__ out) {
    const int tid = threadIdx.x;  // 1024 threads
    float lp = 0.0f, ln = 0.0f;
    int nv = 0;
    for (int j = tid; j < C_; j += 1024) {
        lp += log1pf(g_pos[j]);
        ln += log1pf(g_neg[j]);
        nv += (g_cnt[j] != 0);
    }
#pragma unroll
    for (int o = 16; o > 0; o >>= 1) {
        lp += __shfl_xor_sync(0xffffffffu, lp, o);
        ln += __shfl_xor_sync(0xffffffffu, ln, o);
        nv += __shfl_xor_sync(0xffffffffu, nv, o);
    }
    __shared__ float s_lp[32], s_ln[32];
    __shared__ int   s_nv[32];
    if ((tid & 31) == 0) {
        s_lp[tid >> 5] = lp; s_ln[tid >> 5] = ln; s_nv[tid >> 5] = nv;
    }
    __syncthreads();
    if (tid < 32) {
        lp = s_lp[tid]; ln = s_ln[tid]; nv = s_nv[tid];
#pragma unroll
        for (int o = 16; o > 0; o >>= 1) {
            lp += __shfl_xor_sync(0xffffffffu, lp, o);
            ln += __shfl_xor_sync(0xffffffffu, ln, o);
            nv += __shfl_xor_sync(0xffffffffu, nv, o);
        }
        if (tid == 0) {
            double mm = -(double)32.0 * ((double)dec_f(g_min_u) - 0.1);
            double pos_term = ((double)lp + (double)C_ * mm) / (double)nv;
            double neg_term = ((double)ln + (double)C_ * mm) / (double)C_;
            out[0] = (float)(pos_term + neg_term);
        }
    }
}

// ---------------------------------------------------------------------------
extern "C" void kernel_launch(void* const* d_in, const int* in_sizes, int n_in,
                              void* d_out, int out_size) {
    const float* emb    = (const float*)d_in[0];
    const int*   labels = (const int*)d_in[1];
    const float* mu     = (const float*)d_in[2];
    const float* lv     = (const float*)d_in[3];
    float* out = (float*)d_out;

    k_prep_a<<<(N_ * D_) / 256, 256>>>(emb);
    k_prep_b<<<C_, 32>>>(mu, lv);

    const int smem = (BK * PAD + BK * PB) * (int)sizeof(float);  // 99328 B
    cudaFuncSetAttribute(k_gemm, cudaFuncAttributeMaxDynamicSharedMemorySize, smem);
    k_gemm<<<dim3(C_ / BN, N_ / BM), 256, smem>>>();

    k_colsum<<<dim3(C_ / 128, N_ / 512), 128>>>(labels);
    k_final<<<1, 1024>>>(out);
}

// round 6
// speedup vs baseline: 1.6829x; 1.6829x over previous
#include <cuda_runtime.h>
#include <cstdint>
#include <cstddef>

// ---------------------------------------------------------------------------
// ProxyMLS loss:
//   K1a: pack A[i, 0:64]=e^2, A[i,64:128]=e               (N x 128)
//   K1b: pack B[j, 0:64]=w,  B[j,64:128]=-2*mu*w, cst[j]  (C x 128), zero accums
//   K2 : score = -0.5*(A @ B^T + cst)  -> g_score, + global min (for m)
//   K3 : per-class pos/neg exp sums + counts  (streaming, software exp)
//   K4 : log1p reduction -> scalar
// ---------------------------------------------------------------------------

#define N_ 4096
#define C_ 8192
#define D_ 64
#define KP 128

static __device__ __constant__ float kALPHA  = 32.0f;
static __device__ __constant__ float kMARGIN = 0.1f;

// device scratch (static globals: allocation-free)
__device__ float    g_A[(size_t)N_ * KP];         //  2 MiB
__device__ float    g_B[(size_t)C_ * KP];         //  4 MiB
__device__ float    g_cst[C_];
__device__ float    g_score[(size_t)N_ * C_];     // 128 MiB
__device__ unsigned g_min_u;
__device__ float    g_pos[C_];
__device__ float    g_neg[C_];
__device__ int      g_cnt[C_];

// monotone float <-> unsigned encoding (for atomicMin over floats)
__device__ __forceinline__ unsigned enc_f(float f) {
    unsigned b = __float_as_uint(f);
    return (b & 0x80000000u) ? ~b : (b ^ 0x80000000u);
}
__device__ __forceinline__ float dec_f(unsigned u) {
    unsigned b = (u & 0x80000000u) ? (u ^ 0x80000000u) : ~u;
    return __uint_as_float(b);
}

// packed fp32x2 FMA (Blackwell sm_100+; 2x fp32 throughput, PTX-only)
#define FMA2(d, a, b) asm("fma.rn.f32x2 %0, %1, %2, %0;" : "+l"(d) : "l"(a), "l"(b))

// FMA-pipe exp: avoids MUFU (rt=8/SMSP) and keeps everything on fma/alu.
// Magic-number round-to-int, degree-5 poly for 2^f on [-0.5,0.5],
// exponent spliced via integer add on float bits. Clamped to [-125,125]
// in log2 domain so out-of-range args (discarded by select) stay finite.
__device__ __forceinline__ float fast_exp(float x) {
    float t = x * 1.4426950408889634f;
    t = fminf(fmaxf(t, -125.0f), 125.0f);
    float z = t + 12582912.0f;                  // 1.5 * 2^23 (RN to integer)
    float r = z - 12582912.0f;
    float f = t - r;                            // f in [-0.5, 0.5]
    int  ei = __float_as_int(z) - 0x4B400000;   // (int)r
    float p =            1.33335581464e-3f;
    p = fmaf(p, f,       9.61812910763e-3f);
    p = fmaf(p, f,       5.55041086648e-2f);
    p = fmaf(p, f,       2.40226506959e-1f);
    p = fmaf(p, f,       6.93147180560e-1f);
    p = fmaf(p, f,       1.0f);
    return __int_as_float(__float_as_int(p) + (ei << 23));
}

// ---------------------------------------------------------------------------
// K1a: pack embeddings
__global__ void k_prep_a(const float* __restrict__ emb) {
    int idx = blockIdx.x * 256 + threadIdx.x;   // exactly N_*D_ threads
    int i = idx >> 6;
    int d = idx & 63;
    float e = emb[idx];
    g_A[(size_t)i * KP + d]      = e * e;
    g_A[(size_t)i * KP + 64 + d] = e;
}

// K1b: pack proxies, per-class const, zero accumulators (1 warp per class)
__global__ void k_prep_b(const float* __restrict__ mu_, const float* __restrict__ lv_) {
    int j = blockIdx.x;
    int lane = threadIdx.x;
    float s = 0.0f;
#pragma unroll
    for (int t = 0; t < 2; t++) {
        int d = lane + t * 32;
        float lv = lv_[(size_t)j * D_ + d];
        float mu = mu_[(size_t)j * D_ + d];
        float w  = __expf(-lv);
        g_B[(size_t)j * KP + d]      = w;
        g_B[(size_t)j * KP + 64 + d] = -2.0f * mu * w;
        s += mu * mu * w + lv;
    }
#pragma unroll
    for (int o = 16; o > 0; o >>= 1) s += __shfl_xor_sync(0xffffffffu, s, o);
    if (lane == 0) {
        g_cst[j] = s;
        g_pos[j] = 0.0f;
        g_neg[j] = 0.0f;
        g_cnt[j] = 0;
        if (j == 0) g_min_u = 0xFFFFFFFFu;
    }
}

// ---------------------------------------------------------------------------
// K2: 128x128 block tile, 256 threads, 8x8 per thread via f32x2 pairs.
#define BM 128
#define BN 128
#define BK 64
#define PAD 258   // AsD pitch in floats (2*BM + 2): even -> 8B aligned u64 loads
#define PB  130   // Bs pitch in floats

__global__ void __launch_bounds__(256, 1) k_gemm() {
    extern __shared__ float smem_buf[];
    float* AsD = smem_buf;               // [BK][PAD]  (duplicated A)
    float* Bs  = smem_buf + BK * PAD;    // [BK][PB]

    const int tid = threadIdx.x;
    const int tx  = tid & 15;
    const int ty  = tid >> 4;
    const int m0  = blockIdx.y * BM;
    const int n0  = blockIdx.x * BN;

    unsigned long long acc[8][4];
#pragma unroll
    for (int r = 0; r < 8; r++)
#pragma unroll
        for (int g = 0; g < 4; g++) acc[r][g] = 0ull;

    for (int kc = 0; kc < KP; kc += BK) {
#pragma unroll
        for (int t = 0; t < 8; t++) {
            int fid = tid + t * 256;
            int row = fid >> 4;
            int kq  = fid & 15;
            float4 v = *(const float4*)&g_A[(size_t)(m0 + row) * KP + kc + kq * 4];
            int kb = kq * 4;
            AsD[(kb + 0) * PAD + 2 * row] = v.x; AsD[(kb + 0) * PAD + 2 * row + 1] = v.x;
            AsD[(kb + 1) * PAD + 2 * row] = v.y; AsD[(kb + 1) * PAD + 2 * row + 1] = v.y;
            AsD[(kb + 2) * PAD + 2 * row] = v.z; AsD[(kb + 2) * PAD + 2 * row + 1] = v.z;
            AsD[(kb + 3) * PAD + 2 * row] = v.w; AsD[(kb + 3) * PAD + 2 * row + 1] = v.w;
        }
#pragma unroll
        for (int t = 0; t < 8; t++) {
            int fid = tid + t * 256;
            int row = fid >> 4;
            int kq  = fid & 15;
            float4 v = *(const float4*)&g_B[(size_t)(n0 + row) * KP + kc + kq * 4];
            int kb = kq * 4;
            Bs[(kb + 0) * PB + row] = v.x;
            Bs[(kb + 1) * PB + row] = v.y;
            Bs[(kb + 2) * PB + row] = v.z;
            Bs[(kb + 3) * PB + row] = v.w;
        }
        __syncthreads();

#pragma unroll 16
        for (int k = 0; k < BK; k++) {
            const float* ar = AsD + k * PAD + ty * 4;
            const float* br = Bs  + k * PB  + tx * 2;
            unsigned long long av[8], bv[4];
#pragma unroll
            for (int g = 0; g < 4; g++)
                bv[g] = *(const unsigned long long*)(br + g * 32);
#pragma unroll
            for (int h = 0; h < 4; h++) {
                av[2 * h]     = *(const unsigned long long*)(ar + h * 64);
                av[2 * h + 1] = *(const unsigned long long*)(ar + h * 64 + 2);
            }
#pragma unroll
            for (int r = 0; r < 8; r++)
#pragma unroll
                for (int g = 0; g < 4; g++)
                    FMA2(acc[r][g], av[r], bv[g]);
        }
        __syncthreads();
    }

    // ---- epilogue: score = -0.5*(dot + cst), store + global min ----
    const int cb = n0 + tx * 2;
    float2 cst[4];
#pragma unroll
    for (int g = 0; g < 4; g++)
        cst[g] = *(const float2*)&g_cst[cb + g * 32];

    float mn = 3.402823466e38f;
#pragma unroll
    for (int h = 0; h < 4; h++) {
#pragma unroll
        for (int rr = 0; rr < 2; rr++) {
            int row = m0 + h * 32 + ty * 2 + rr;
            int r = h * 2 + rr;
            float* dst = &g_score[(size_t)row * C_ + cb];
#pragma unroll
            for (int g = 0; g < 4; g++) {
                float lo = __uint_as_float((unsigned)(acc[r][g] & 0xffffffffu));
                float hi = __uint_as_float((unsigned)(acc[r][g] >> 32));
                float s0 = -0.5f * (lo + cst[g].x);
                float s1 = -0.5f * (hi + cst[g].y);
                mn = fminf(mn, fminf(s0, s1));
                *(float2*)(dst + g * 32) = make_float2(s0, s1);
            }
        }
    }

#pragma unroll
    for (int o = 16; o > 0; o >>= 1)
        mn = fminf(mn, __shfl_xor_sync(0xffffffffu, mn, o));
    __shared__ float smin[8];
    if ((tid & 31) == 0) smin[tid >> 5] = mn;
    __syncthreads();
    if (tid < 8) {
        mn = smin[tid];
#pragma unroll
        for (int o = 4; o > 0; o >>= 1)
            mn = fminf(mn, __shfl_xor_sync(0xffu, mn, o));
        if (tid == 0) atomicMin(&g_min_u, enc_f(mn));
    }
}

// ---------------------------------------------------------------------------
// K3: streaming per-class exp sums.
// Block: 256 threads x 4 cols each (1024 cols), 64 rows per block.
// Loads front-batched 8-deep (float4) for MLP; exp on the FMA pipe.
#define K3_COLS 1024
#define K3_ROWS 64

__global__ void __launch_bounds__(256) k_colsum(const int* __restrict__ labels) {
    __shared__ int s_lab[K3_ROWS];
    const int tid = threadIdx.x;
    const int j0  = blockIdx.x * K3_COLS + tid * 4;
    const int i0  = blockIdx.y * K3_ROWS;
    if (tid < K3_ROWS) s_lab[tid] = labels[i0 + tid];
    __syncthreads();

    const float m  = -kALPHA * (dec_f(g_min_u) - kMARGIN);  // m = max(pos_e)
    const float cb = kALPHA * kMARGIN - m;                  // shared affine const

    float ng0 = 0.f, ng1 = 0.f, ng2 = 0.f, ng3 = 0.f;
    float ps0 = 0.f, ps1 = 0.f, ps2 = 0.f, ps3 = 0.f;
    int   ct0 = 0,   ct1 = 0,   ct2 = 0,   ct3 = 0;

    const float* base = g_score + (size_t)i0 * C_ + j0;

#pragma unroll
    for (int ib = 0; ib < K3_ROWS; ib += 8) {
        float4 xs[8];
#pragma unroll
        for (int u = 0; u < 8; u++)
            xs[u] = *(const float4*)(base + (size_t)(ib + u) * C_);
#pragma unroll
        for (int u = 0; u < 8; u++) {
            const int   lab = s_lab[ib + u];
            const float4 x  = xs[u];
            float e0 = fast_exp(fmaf(kALPHA, x.x, cb));
            float e1 = fast_exp(fmaf(kALPHA, x.y, cb));
            float e2 = fast_exp(fmaf(kALPHA, x.z, cb));
            float e3 = fast_exp(fmaf(kALPHA, x.w, cb));
            int c = lab - j0;
            ng0 += (c == 0) ? 0.f : e0;
            ng1 += (c == 1) ? 0.f : e1;
            ng2 += (c == 2) ? 0.f : e2;
            ng3 += (c == 3) ? 0.f : e3;
            if ((unsigned)c < 4u) {   // rare: one per row over all C
                float xv = (c == 0) ? x.x : (c == 1) ? x.y : (c == 2) ? x.z : x.w;
                float pv = fast_exp(fmaf(-kALPHA, xv, cb));
                if      (c == 0) { ps0 += pv; ct0++; }
                else if (c == 1) { ps1 += pv; ct1++; }
                else if (c == 2) { ps2 += pv; ct2++; }
                else             { ps3 += pv; ct3++; }
            }
        }
    }

    atomicAdd(&g_neg[j0 + 0], ng0);
    atomicAdd(&g_neg[j0 + 1], ng1);
    atomicAdd(&g_neg[j0 + 2], ng2);
    atomicAdd(&g_neg[j0 + 3], ng3);
    if (ct0) { atomicAdd(&g_cnt[j0 + 0], ct0); atomicAdd(&g_pos[j0 + 0], ps0); }
    if (ct1) { atomicAdd(&g_cnt[j0 + 1], ct1); atomicAdd(&g_pos[j0 + 1], ps1); }
    if (ct2) { atomicAdd(&g_cnt[j0 + 2], ct2); atomicAdd(&g_pos[j0 + 2], ps2); }
    if (ct3) { atomicAdd(&g_cnt[j0 + 3], ct3); atomicAdd(&g_pos[j0 + 3], ps3); }
}

// ---------------------------------------------------------------------------
// K4: final scalar
__global__ void k_final(float* __restrict__ out) {
    const int tid = threadIdx.x;  // 1024 threads
    float lp = 0.0f, ln = 0.0f;
    int nv = 0;
    for (int j = tid; j < C_; j += 1024) {
        lp += log1pf(g_pos[j]);
        ln += log1pf(g_neg[j]);
        nv += (g_cnt[j] != 0);
    }
#pragma unroll
    for (int o = 16; o > 0; o >>= 1) {
        lp += __shfl_xor_sync(0xffffffffu, lp, o);
        ln += __shfl_xor_sync(0xffffffffu, ln, o);
        nv += __shfl_xor_sync(0xffffffffu, nv, o);
    }
    __shared__ float s_lp[32], s_ln[32];
    __shared__ int   s_nv[32];
    if ((tid & 31) == 0) {
        s_lp[tid >> 5] = lp; s_ln[tid >> 5] = ln; s_nv[tid >> 5] = nv;
    }
    __syncthreads();
    if (tid < 32) {
        lp = s_lp[tid]; ln = s_ln[tid]; nv = s_nv[tid];
#pragma unroll
        for (int o = 16; o > 0; o >>= 1) {
            lp += __shfl_xor_sync(0xffffffffu, lp, o);
            ln += __shfl_xor_sync(0xffffffffu, ln, o);
            nv += __shfl_xor_sync(0xffffffffu, nv, o);
        }
        if (tid == 0) {
            double mm = -(double)32.0 * ((double)dec_f(g_min_u) - 0.1);
            double pos_term = ((double)lp + (double)C_ * mm) / (double)nv;
            double neg_term = ((double)ln + (double)C_ * mm) / (double)C_;
            out[0] = (float)(pos_term + neg_term);
        }
    }
}

// ---------------------------------------------------------------------------
extern "C" void kernel_launch(void* const* d_in, const int* in_sizes, int n_in,
                              void* d_out, int out_size) {
    const float* emb    = (const float*)d_in[0];
    const int*   labels = (const int*)d_in[1];
    const float* mu     = (const float*)d_in[2];
    const float* lv     = (const float*)d_in[3];
    float* out = (float*)d_out;

    k_prep_a<<<(N_ * D_) / 256, 256>>>(emb);
    k_prep_b<<<C_, 32>>>(mu, lv);

    const int smem = (BK * PAD + BK * PB) * (int)sizeof(float);  // 99328 B
    cudaFuncSetAttribute(k_gemm, cudaFuncAttributeMaxDynamicSharedMemorySize, smem);
    k_gemm<<<dim3(C_ / BN, N_ / BM), 256, smem>>>();

    k_colsum<<<dim3(C_ / K3_COLS, N_ / K3_ROWS), 256>>>(labels);
    k_final<<<1, 1024>>>(out);
}

// round 7
// speedup vs baseline: 1.6831x; 1.0001x over previous
#include <cuda_runtime.h>
#include <cstdint>
#include <cstddef>

// ---------------------------------------------------------------------------
// ProxyMLS loss:
//   K1a: pack A[i, 0:64]=e^2, A[i,64:128]=e               (N x 128)
//   K1b: pack B[j, 0:64]=w,  B[j,64:128]=-2*mu*w, cst[j]  (C x 128), zero accums
//   K2 : score = -0.5*(A @ B^T + cst)  -> g_score, + global min (for m)
//   K3 : per-class pos/neg exp sums + counts  (streaming, software exp)
//   K4 : log1p reduction -> scalar
// ---------------------------------------------------------------------------

#define N_ 4096
#define C_ 8192
#define D_ 64
#define KP 128

static __device__ __constant__ float kALPHA  = 32.0f;
static __device__ __constant__ float kMARGIN = 0.1f;

// device scratch (static globals: allocation-free)
__device__ float    g_A[(size_t)N_ * KP];         //  2 MiB
__device__ float    g_B[(size_t)C_ * KP];         //  4 MiB
__device__ float    g_cst[C_];
__device__ float    g_score[(size_t)N_ * C_];     // 128 MiB
__device__ unsigned g_min_u;
__device__ float    g_pos[C_];
__device__ float    g_neg[C_];
__device__ int      g_cnt[C_];

// monotone float <-> unsigned encoding (for atomicMin over floats)
__device__ __forceinline__ unsigned enc_f(float f) {
    unsigned b = __float_as_uint(f);
    return (b & 0x80000000u) ? ~b : (b ^ 0x80000000u);
}
__device__ __forceinline__ float dec_f(unsigned u) {
    unsigned b = (u & 0x80000000u) ? (u ^ 0x80000000u) : ~u;
    return __uint_as_float(b);
}

// packed fp32x2 FMA (Blackwell sm_100+; 2x fp32 throughput, PTX-only)
#define FMA2(d, a, b) asm("fma.rn.f32x2 %0, %1, %2, %0;" : "+l"(d) : "l"(a), "l"(b))

// FMA-pipe exp: avoids MUFU (rt=8/SMSP) and keeps everything on fma/alu.
// Magic-number round-to-int, degree-5 poly for 2^f on [-0.5,0.5],
// exponent spliced via integer add on float bits. Clamped to [-125,125]
// in log2 domain so out-of-range args (discarded by select) stay finite.
__device__ __forceinline__ float fast_exp(float x) {
    float t = x * 1.4426950408889634f;
    t = fminf(fmaxf(t, -125.0f), 125.0f);
    float z = t + 12582912.0f;                  // 1.5 * 2^23 (RN to integer)
    float r = z - 12582912.0f;
    float f = t - r;                            // f in [-0.5, 0.5]
    int  ei = __float_as_int(z) - 0x4B400000;   // (int)r
    float p =            1.33335581464e-3f;
    p = fmaf(p, f,       9.61812910763e-3f);
    p = fmaf(p, f,       5.55041086648e-2f);
    p = fmaf(p, f,       2.40226506959e-1f);
    p = fmaf(p, f,       6.93147180560e-1f);
    p = fmaf(p, f,       1.0f);
    return __int_as_float(__float_as_int(p) + (ei << 23));
}

// ---------------------------------------------------------------------------
// K1a: pack embeddings
__global__ void k_prep_a(const float* __restrict__ emb) {
    int idx = blockIdx.x * 256 + threadIdx.x;   // exactly N_*D_ threads
    int i = idx >> 6;
    int d = idx & 63;
    float e = emb[idx];
    g_A[(size_t)i * KP + d]      = e * e;
    g_A[(size_t)i * KP + 64 + d] = e;
}

// K1b: pack proxies, per-class const, zero accumulators (1 warp per class)
__global__ void k_prep_b(const float* __restrict__ mu_, const float* __restrict__ lv_) {
    int j = blockIdx.x;
    int lane = threadIdx.x;
    float s = 0.0f;
#pragma unroll
    for (int t = 0; t < 2; t++) {
        int d = lane + t * 32;
        float lv = lv_[(size_t)j * D_ + d];
        float mu = mu_[(size_t)j * D_ + d];
        float w  = __expf(-lv);
        g_B[(size_t)j * KP + d]      = w;
        g_B[(size_t)j * KP + 64 + d] = -2.0f * mu * w;
        s += mu * mu * w + lv;
    }
#pragma unroll
    for (int o = 16; o > 0; o >>= 1) s += __shfl_xor_sync(0xffffffffu, s, o);
    if (lane == 0) {
        g_cst[j] = s;
        g_pos[j] = 0.0f;
        g_neg[j] = 0.0f;
        g_cnt[j] = 0;
        if (j == 0) g_min_u = 0xFFFFFFFFu;
    }
}

// ---------------------------------------------------------------------------
// K2: 128x128 block tile, 256 threads, 8x8 per thread via f32x2 pairs.
#define BM 128
#define BN 128
#define BK 64
#define PAD 258   // AsD pitch in floats (2*BM + 2): even -> 8B aligned u64 loads
#define PB  130   // Bs pitch in floats

__global__ void __launch_bounds__(256, 1) k_gemm() {
    extern __shared__ float smem_buf[];
    float* AsD = smem_buf;               // [BK][PAD]  (duplicated A)
    float* Bs  = smem_buf + BK * PAD;    // [BK][PB]

    const int tid = threadIdx.x;
    const int tx  = tid & 15;
    const int ty  = tid >> 4;
    const int m0  = blockIdx.y * BM;
    const int n0  = blockIdx.x * BN;

    unsigned long long acc[8][4];
#pragma unroll
    for (int r = 0; r < 8; r++)
#pragma unroll
        for (int g = 0; g < 4; g++) acc[r][g] = 0ull;

    for (int kc = 0; kc < KP; kc += BK) {
#pragma unroll
        for (int t = 0; t < 8; t++) {
            int fid = tid + t * 256;
            int row = fid >> 4;
            int kq  = fid & 15;
            float4 v = *(const float4*)&g_A[(size_t)(m0 + row) * KP + kc + kq * 4];
            int kb = kq * 4;
            AsD[(kb + 0) * PAD + 2 * row] = v.x; AsD[(kb + 0) * PAD + 2 * row + 1] = v.x;
            AsD[(kb + 1) * PAD + 2 * row] = v.y; AsD[(kb + 1) * PAD + 2 * row + 1] = v.y;
            AsD[(kb + 2) * PAD + 2 * row] = v.z; AsD[(kb + 2) * PAD + 2 * row + 1] = v.z;
            AsD[(kb + 3) * PAD + 2 * row] = v.w; AsD[(kb + 3) * PAD + 2 * row + 1] = v.w;
        }
#pragma unroll
        for (int t = 0; t < 8; t++) {
            int fid = tid + t * 256;
            int row = fid >> 4;
            int kq  = fid & 15;
            float4 v = *(const float4*)&g_B[(size_t)(n0 + row) * KP + kc + kq * 4];
            int kb = kq * 4;
            Bs[(kb + 0) * PB + row] = v.x;
            Bs[(kb + 1) * PB + row] = v.y;
            Bs[(kb + 2) * PB + row] = v.z;
            Bs[(kb + 3) * PB + row] = v.w;
        }
        __syncthreads();

#pragma unroll 16
        for (int k = 0; k < BK; k++) {
            const float* ar = AsD + k * PAD + ty * 4;
            const float* br = Bs  + k * PB  + tx * 2;
            unsigned long long av[8], bv[4];
#pragma unroll
            for (int g = 0; g < 4; g++)
                bv[g] = *(const unsigned long long*)(br + g * 32);
#pragma unroll
            for (int h = 0; h < 4; h++) {
                av[2 * h]     = *(const unsigned long long*)(ar + h * 64);
                av[2 * h + 1] = *(const unsigned long long*)(ar + h * 64 + 2);
            }
#pragma unroll
            for (int r = 0; r < 8; r++)
#pragma unroll
                for (int g = 0; g < 4; g++)
                    FMA2(acc[r][g], av[r], bv[g]);
        }
        __syncthreads();
    }

    // ---- epilogue: score = -0.5*(dot + cst), store + global min ----
    const int cb = n0 + tx * 2;
    float2 cst[4];
#pragma unroll
    for (int g = 0; g < 4; g++)
        cst[g] = *(const float2*)&g_cst[cb + g * 32];

    float mn = 3.402823466e38f;
#pragma unroll
    for (int h = 0; h < 4; h++) {
#pragma unroll
        for (int rr = 0; rr < 2; rr++) {
            int row = m0 + h * 32 + ty * 2 + rr;
            int r = h * 2 + rr;
            float* dst = &g_score[(size_t)row * C_ + cb];
#pragma unroll
            for (int g = 0; g < 4; g++) {
                float lo = __uint_as_float((unsigned)(acc[r][g] & 0xffffffffu));
                float hi = __uint_as_float((unsigned)(acc[r][g] >> 32));
                float s0 = -0.5f * (lo + cst[g].x);
                float s1 = -0.5f * (hi + cst[g].y);
                mn = fminf(mn, fminf(s0, s1));
                *(float2*)(dst + g * 32) = make_float2(s0, s1);
            }
        }
    }

#pragma unroll
    for (int o = 16; o > 0; o >>= 1)
        mn = fminf(mn, __shfl_xor_sync(0xffffffffu, mn, o));
    __shared__ float smin[8];
    if ((tid & 31) == 0) smin[tid >> 5] = mn;
    __syncthreads();
    if (tid < 8) {
        mn = smin[tid];
#pragma unroll
        for (int o = 4; o > 0; o >>= 1)
            mn = fminf(mn, __shfl_xor_sync(0xffu, mn, o));
        if (tid == 0) atomicMin(&g_min_u, enc_f(mn));
    }
}

// ---------------------------------------------------------------------------
// K3: streaming per-class exp sums.
// Block: 256 threads x 4 cols each (1024 cols), 64 rows per block.
// Loads front-batched 8-deep (float4) for MLP; exp on the FMA pipe.
#define K3_COLS 1024
#define K3_ROWS 64

__global__ void __launch_bounds__(256) k_colsum(const int* __restrict__ labels) {
    __shared__ int s_lab[K3_ROWS];
    const int tid = threadIdx.x;
    const int j0  = blockIdx.x * K3_COLS + tid * 4;
    const int i0  = blockIdx.y * K3_ROWS;
    if (tid < K3_ROWS) s_lab[tid] = labels[i0 + tid];
    __syncthreads();

    const float m  = -kALPHA * (dec_f(g_min_u) - kMARGIN);  // m = max(pos_e)
    const float cb = kALPHA * kMARGIN - m;                  // shared affine const

    float ng0 = 0.f, ng1 = 0.f, ng2 = 0.f, ng3 = 0.f;
    float ps0 = 0.f, ps1 = 0.f, ps2 = 0.f, ps3 = 0.f;
    int   ct0 = 0,   ct1 = 0,   ct2 = 0,   ct3 = 0;

    const float* base = g_score + (size_t)i0 * C_ + j0;

#pragma unroll
    for (int ib = 0; ib < K3_ROWS; ib += 8) {
        float4 xs[8];
#pragma unroll
        for (int u = 0; u < 8; u++)
            xs[u] = *(const float4*)(base + (size_t)(ib + u) * C_);
#pragma unroll
        for (int u = 0; u < 8; u++) {
            const int   lab = s_lab[ib + u];
            const float4 x  = xs[u];
            float e0 = fast_exp(fmaf(kALPHA, x.x, cb));
            float e1 = fast_exp(fmaf(kALPHA, x.y, cb));
            float e2 = fast_exp(fmaf(kALPHA, x.z, cb));
            float e3 = fast_exp(fmaf(kALPHA, x.w, cb));
            int c = lab - j0;
            ng0 += (c == 0) ? 0.f : e0;
            ng1 += (c == 1) ? 0.f : e1;
            ng2 += (c == 2) ? 0.f : e2;
            ng3 += (c == 3) ? 0.f : e3;
            if ((unsigned)c < 4u) {   // rare: one per row over all C
                float xv = (c == 0) ? x.x : (c == 1) ? x.y : (c == 2) ? x.z : x.w;
                float pv = fast_exp(fmaf(-kALPHA, xv, cb));
                if      (c == 0) { ps0 += pv; ct0++; }
                else if (c == 1) { ps1 += pv; ct1++; }
                else if (c == 2) { ps2 += pv; ct2++; }
                else             { ps3 += pv; ct3++; }
            }
        }
    }

    atomicAdd(&g_neg[j0 + 0], ng0);
    atomicAdd(&g_neg[j0 + 1], ng1);
    atomicAdd(&g_neg[j0 + 2], ng2);
    atomicAdd(&g_neg[j0 + 3], ng3);
    if (ct0) { atomicAdd(&g_cnt[j0 + 0], ct0); atomicAdd(&g_pos[j0 + 0], ps0); }
    if (ct1) { atomicAdd(&g_cnt[j0 + 1], ct1); atomicAdd(&g_pos[j0 + 1], ps1); }
    if (ct2) { atomicAdd(&g_cnt[j0 + 2], ct2); atomicAdd(&g_pos[j0 + 2], ps2); }
    if (ct3) { atomicAdd(&g_cnt[j0 + 3], ct3); atomicAdd(&g_pos[j0 + 3], ps3); }
}

// ---------------------------------------------------------------------------
// K4: final scalar
__global__ void k_final(float* __restrict__ out) {
    const int tid = threadIdx.x;  // 1024 threads
    float lp = 0.0f, ln = 0.0f;
    int nv = 0;
    for (int j = tid; j < C_; j += 1024) {
        lp += log1pf(g_pos[j]);
        ln += log1pf(g_neg[j]);
        nv += (g_cnt[j] != 0);
    }
#pragma unroll
    for (int o = 16; o > 0; o >>= 1) {
        lp += __shfl_xor_sync(0xffffffffu, lp, o);
        ln += __shfl_xor_sync(0xffffffffu, ln, o);
        nv += __shfl_xor_sync(0xffffffffu, nv, o);
    }
    __shared__ float s_lp[32], s_ln[32];
    __shared__ int   s_nv[32];
    if ((tid & 31) == 0) {
        s_lp[tid >> 5] = lp; s_ln[tid >> 5] = ln; s_nv[tid >> 5] = nv;
    }
    __syncthreads();
    if (tid < 32) {
        lp = s_lp[tid]; ln = s_ln[tid]; nv = s_nv[tid];
#pragma unroll
        for (int o = 16; o > 0; o >>= 1) {
            lp += __shfl_xor_sync(0xffffffffu, lp, o);
            ln += __shfl_xor_sync(0xffffffffu, ln, o);
            nv += __shfl_xor_sync(0xffffffffu, nv, o);
        }
        if (tid == 0) {
            double mm = -(double)32.0 * ((double)dec_f(g_min_u) - 0.1);
            double pos_term = ((double)lp + (double)C_ * mm) / (double)nv;
            double neg_term = ((double)ln + (double)C_ * mm) / (double)C_;
            out[0] = (float)(pos_term + neg_term);
        }
    }
}

// ---------------------------------------------------------------------------
extern "C" void kernel_launch(void* const* d_in, const int* in_sizes, int n_in,
                              void* d_out, int out_size) {
    const float* emb    = (const float*)d_in[0];
    const int*   labels = (const int*)d_in[1];
    const float* mu     = (const float*)d_in[2];
    const float* lv     = (const float*)d_in[3];
    float* out = (float*)d_out;

    k_prep_a<<<(N_ * D_) / 256, 256>>>(emb);
    k_prep_b<<<C_, 32>>>(mu, lv);

    const int smem = (BK * PAD + BK * PB) * (int)sizeof(float);  // 99328 B
    cudaFuncSetAttribute(k_gemm, cudaFuncAttributeMaxDynamicSharedMemorySize, smem);
    k_gemm<<<dim3(C_ / BN, N_ / BM), 256, smem>>>();

    k_colsum<<<dim3(C_ / K3_COLS, N_ / K3_ROWS), 256>>>(labels);
    k_final<<<1, 1024>>>(out);
}